// round 17
// baseline (speedup 1.0000x reference)
#include <cuda_runtime.h>
#include <math.h>
#include <stdint.h>

// Problem constants (fixed by setup_inputs)
#define DMODEL 1024
#define NHEADS 16
#define DKH    64
#define SEQ    2048
#define BATCH  2
#define MROWS  (BATCH*SEQ)   // 4096
#define DFF    4096

// ---------------- scratch (device globals: allocation-guard safe) ----------
__device__ float g_h [MROWS*DMODEL];
__device__ float g_q [MROWS*DMODEL];
__device__ float g_k [MROWS*DMODEL];
__device__ float g_v [MROWS*DMODEL];
__device__ float g_a [MROWS*DMODEL];
__device__ float g_x2[MROWS*DMODEL];
__device__ float g_f1[MROWS*DFF];

// ---------------- PTX helpers ----------------------------------------------
__device__ __forceinline__ uint32_t f2tf(float f) {
    uint32_t u;
    asm("cvt.rna.tf32.f32 %0, %1;" : "=r"(u) : "f"(f));
    return u;
}
__device__ __forceinline__ void ldsm4(uint32_t r[4], uint32_t addr) {
    asm volatile("ldmatrix.sync.aligned.m8n8.x4.shared.b16 {%0,%1,%2,%3}, [%4];"
                 : "=r"(r[0]), "=r"(r[1]), "=r"(r[2]), "=r"(r[3]) : "r"(addr));
}
__device__ __forceinline__ void mma_tf32(float c[4], const uint32_t a[4], uint32_t b0, uint32_t b1) {
    asm volatile("mma.sync.aligned.m16n8k8.row.col.f32.tf32.tf32.f32 "
                 "{%0,%1,%2,%3}, {%4,%5,%6,%7}, {%8,%9}, {%0,%1,%2,%3};"
                 : "+f"(c[0]), "+f"(c[1]), "+f"(c[2]), "+f"(c[3])
                 : "r"(a[0]), "r"(a[1]), "r"(a[2]), "r"(a[3]), "r"(b0), "r"(b1));
}
__device__ __forceinline__ void cp16(uint32_t dst, const void* src) {
    asm volatile("cp.async.ca.shared.global [%0], [%1], 16;" :: "r"(dst), "l"(src));
}

// ---------------- LayerNorm -------------------------------------------------
__global__ __launch_bounds__(256) void layernorm_k(
    const float* __restrict__ x, const float* __restrict__ gamma,
    const float* __restrict__ beta, float* __restrict__ out)
{
    int row = blockIdx.x;
    int tid = threadIdx.x;
    const float4* xr = (const float4*)(x + (size_t)row * DMODEL);
    float4 v = xr[tid];
    float s  = v.x + v.y + v.z + v.w;
    float ss = v.x*v.x + v.y*v.y + v.z*v.z + v.w*v.w;
    #pragma unroll
    for (int o = 16; o > 0; o >>= 1) {
        s  += __shfl_xor_sync(0xffffffffu, s,  o);
        ss += __shfl_xor_sync(0xffffffffu, ss, o);
    }
    __shared__ float sred[8], ssred[8];
    int w = tid >> 5;
    if ((tid & 31) == 0) { sred[w] = s; ssred[w] = ss; }
    __syncthreads();
    float tot = 0.f, tot2 = 0.f;
    #pragma unroll
    for (int i = 0; i < 8; i++) { tot += sred[i]; tot2 += ssred[i]; }
    float mu  = tot  * (1.0f / DMODEL);
    float var = tot2 * (1.0f / DMODEL) - mu * mu;
    float inv = rsqrtf(var + 1e-5f);
    float4 gg = ((const float4*)gamma)[tid];
    float4 bb = ((const float4*)beta)[tid];
    float4 o;
    o.x = (v.x - mu) * inv * gg.x + bb.x;
    o.y = (v.y - mu) * inv * gg.y + bb.y;
    o.z = (v.z - mu) * inv * gg.z + bb.z;
    o.w = (v.w - mu) * inv * gg.w + bb.w;
    ((float4*)(out + (size_t)row * DMODEL))[tid] = o;
}

// ---------------- tf32 TC NT GEMM, cp.async double-buffered BK=16 ----------
// C[M,N] = A[M,K]*B[N,K]^T (+bias, +relu-then-res). 128x128 tile, 256 thr,
// 8 warps 2(M)x4(N), warp tile 64x32. Swizzle: ch = c4 ^ ((r>>1)&3).
// fp32 bits fed directly to mma.tf32 (truncated tf32); LDSM addrs hoisted.
#define STAGE_BYTES (128*16*4)
template<bool RELU, bool RES>
__global__ __launch_bounds__(256) void gemm_tc(
    const float* __restrict__ A, const float* __restrict__ B,
    const float* __restrict__ bias, const float* __restrict__ res,
    float* __restrict__ C, int M, int N, int K)
{
    __shared__ __align__(16) float As[2][128*16];
    __shared__ __align__(16) float Bs[2][128*16];
    const int t = threadIdx.x;
    const int warp = t >> 5, lane = t & 31;
    const int wm = (warp >> 2) * 64;
    const int wn = (warp & 3) * 32;
    const int bm = blockIdx.y * 128, bn = blockIdx.x * 128;

    uint32_t sA = (uint32_t)__cvta_generic_to_shared(As);
    uint32_t sB = (uint32_t)__cvta_generic_to_shared(Bs);

    float acc[4][4][4];
    #pragma unroll
    for (int mt = 0; mt < 4; mt++)
        #pragma unroll
        for (int nt = 0; nt < 4; nt++)
            #pragma unroll
            for (int i = 0; i < 4; i++) acc[mt][nt][i] = 0.f;

    // loader thread mapping: 2 x 16B chunks per matrix per stage.
    const int r0l = t >> 2,   c0l = t & 3;      // rows 0..63
    const int r1l = r0l + 64;                   // rows 64..127
    const int ch0 = c0l ^ ((r0l >> 1) & 3);
    const int ch1 = c0l ^ ((r1l >> 1) & 3);
    const uint32_t dA0 = sA + (uint32_t)(r0l * 16 + ch0 * 4) * 4u;
    const uint32_t dA1 = sA + (uint32_t)(r1l * 16 + ch1 * 4) * 4u;
    const uint32_t dB0 = sB + (uint32_t)(r0l * 16 + ch0 * 4) * 4u;
    const uint32_t dB1 = sB + (uint32_t)(r1l * 16 + ch1 * 4) * 4u;
    const float* gA0 = A + (size_t)(bm + r0l) * K + c0l * 4;
    const float* gA1 = A + (size_t)(bm + r1l) * K + c0l * 4;
    const float* gB0 = B + (size_t)(bn + r0l) * K + c0l * 4;
    const float* gB1 = B + (size_t)(bn + r1l) * K + c0l * 4;

    // hoisted LDSM addresses (buffer 0; add bufOff in loop)
    uint32_t bAddr[4], aAddr[2][4];
    #pragma unroll
    for (int nt = 0; nt < 4; nt++) {
        int row = wn + nt * 8 + (lane & 7);
        int ch  = (lane >> 3) ^ ((row >> 1) & 3);
        bAddr[nt] = sB + (uint32_t)(row * 16 + ch * 4) * 4u;
    }
    #pragma unroll
    for (int ks = 0; ks < 2; ks++)
        #pragma unroll
        for (int mt = 0; mt < 4; mt++) {
            int row = wm + mt * 16 + (lane & 15);
            int ch  = (ks * 2 + (lane >> 4)) ^ ((row >> 1) & 3);
            aAddr[ks][mt] = sA + (uint32_t)(row * 16 + ch * 4) * 4u;
        }

    // prologue: stage 0 loads
    cp16(dA0, gA0); cp16(dA1, gA1); cp16(dB0, gB0); cp16(dB1, gB1);
    asm volatile("cp.async.commit_group;");

    const int nstages = K >> 4;
    for (int s = 0; s < nstages; s++) {
        const uint32_t bufOff = (uint32_t)(s & 1) * STAGE_BYTES;
        if (s + 1 < nstages) {
            const uint32_t nOff = (uint32_t)((s + 1) & 1) * STAGE_BYTES;
            const int ko = (s + 1) << 4;
            cp16(dA0 + nOff, gA0 + ko); cp16(dA1 + nOff, gA1 + ko);
            cp16(dB0 + nOff, gB0 + ko); cp16(dB1 + nOff, gB1 + ko);
            asm volatile("cp.async.commit_group;");
            asm volatile("cp.async.wait_group 1;");
        } else {
            asm volatile("cp.async.wait_group 0;");
        }
        __syncthreads();

        uint32_t bfr[4][4];
        #pragma unroll
        for (int nt = 0; nt < 4; nt++)
            ldsm4(bfr[nt], bAddr[nt] + bufOff);
        #pragma unroll
        for (int ks = 0; ks < 2; ks++) {
            uint32_t afr[4][4];
            #pragma unroll
            for (int mt = 0; mt < 4; mt++)
                ldsm4(afr[mt], aAddr[ks][mt] + bufOff);
            #pragma unroll
            for (int mt = 0; mt < 4; mt++)
                #pragma unroll
                for (int nt = 0; nt < 4; nt++)
                    mma_tf32(acc[mt][nt], afr[mt], bfr[nt][ks*2], bfr[nt][ks*2+1]);
        }
        __syncthreads();
    }

    // epilogue
    const int gr = lane >> 2, tg = lane & 3;
    #pragma unroll
    for (int mt = 0; mt < 4; mt++) {
        #pragma unroll
        for (int nt = 0; nt < 4; nt++) {
            int r0 = bm + wm + mt * 16 + gr;
            int c0 = bn + wn + nt * 8 + 2 * tg;
            float2 bval = {0.f, 0.f};
            if (bias) bval = *(const float2*)(bias + c0);
            #pragma unroll
            for (int half = 0; half < 2; half++) {
                int r = r0 + half * 8;
                float o0 = acc[mt][nt][half*2+0] + bval.x;
                float o1 = acc[mt][nt][half*2+1] + bval.y;
                if (RELU) { o0 = fmaxf(o0, 0.f); o1 = fmaxf(o1, 0.f); }
                if (RES) {
                    float2 rv = *(const float2*)(res + (size_t)r * N + c0);
                    o0 += rv.x; o1 += rv.y;
                }
                float2 ov = {o0, o1};
                *(float2*)(C + (size_t)r * N + c0) = ov;
            }
        }
    }
}

// ---------------- tf32 tensor-core flash attention (unchanged) -------------
// Block: 128 thr (4 warps), 64 q rows (16 per warp). KV tiles of 64. dk=64.
#define APAD 68
__global__ __launch_bounds__(128) void attn_tc(
    const float* __restrict__ Q, const float* __restrict__ K,
    const float* __restrict__ V, const unsigned char* __restrict__ mask,
    float* __restrict__ O)
{
    __shared__ __align__(16) uint32_t Ks[64*APAD];
    __shared__ __align__(16) uint32_t Vt[64*APAD];
    __shared__ unsigned char msk[64];

    const int t = threadIdx.x, warp = t >> 5, lane = t & 31;
    const int gr = lane >> 2, tg = lane & 3;
    const int b = blockIdx.y >> 4, h = blockIdx.y & 15;
    const int q0 = blockIdx.x * 64;
    const int qw = q0 + warp * 16;
    const size_t baseKV = ((size_t)(b * SEQ)) * DMODEL + h * DKH;

    uint32_t sK = (uint32_t)__cvta_generic_to_shared(Ks);
    uint32_t sV = (uint32_t)__cvta_generic_to_shared(Vt);

    uint32_t qa[8][4];
    {
        const float* Qb = Q + ((size_t)(b * SEQ + qw)) * DMODEL + h * DKH;
        const float* r0 = Qb + (size_t)gr * DMODEL;
        const float* r1 = Qb + (size_t)(gr + 8) * DMODEL;
        #pragma unroll
        for (int ks = 0; ks < 8; ks++) {
            qa[ks][0] = f2tf(r0[ks*8 + tg]);
            qa[ks][1] = f2tf(r1[ks*8 + tg]);
            qa[ks][2] = f2tf(r0[ks*8 + tg + 4]);
            qa[ks][3] = f2tf(r1[ks*8 + tg + 4]);
        }
    }

    float m0 = -INFINITY, m1 = -INFINITY, l0 = 0.f, l1 = 0.f;
    float oacc[8][4];
    #pragma unroll
    for (int i = 0; i < 8; i++)
        #pragma unroll
        for (int j = 0; j < 4; j++) oacc[i][j] = 0.f;

    const int ga = (lane >> 2) + ((warp & 1) << 3);
    const int gb = (lane & 3) + ((warp >> 1) << 2);
    const int qb = lane & ~3;

    for (int kv0 = 0; kv0 < SEQ; kv0 += 64) {
        {
            const float* Kg = K + baseKV + (size_t)kv0 * DMODEL;
            #pragma unroll
            for (int i = 0; i < 8; i++) {
                int idx = i * 128 + t;
                int r = idx >> 4, c4 = idx & 15;
                float4 kv4 = *(const float4*)(Kg + (size_t)r * DMODEL + c4 * 4);
                uint4 o = {f2tf(kv4.x), f2tf(kv4.y), f2tf(kv4.z), f2tf(kv4.w)};
                *(uint4*)&Ks[r * APAD + c4 * 4] = o;
            }
        }
        {
            const float* Vg = V + baseKV + (size_t)kv0 * DMODEL;
            #pragma unroll
            for (int pass = 0; pass < 2; pass++) {
                int bb = gb + pass * 8;
                float4 vr[4];
                #pragma unroll
                for (int j = 0; j < 4; j++)
                    vr[j] = *(const float4*)(Vg + (size_t)(bb*4 + j) * DMODEL + ga * 4);
                const float* f0 = (const float*)&vr[0];
                const float* f1 = (const float*)&vr[1];
                const float* f2 = (const float*)&vr[2];
                const float* f3 = (const float*)&vr[3];
                #pragma unroll
                for (int i = 0; i < 4; i++) {
                    uint4 o = {f2tf(f0[i]), f2tf(f1[i]), f2tf(f2[i]), f2tf(f3[i])};
                    *(uint4*)&Vt[(ga*4 + i) * APAD + bb*4] = o;
                }
            }
        }
        if (t < 16)
            ((uint32_t*)msk)[t] = ((const uint32_t*)(mask + (size_t)b * SEQ + kv0))[t];
        __syncthreads();

        float sc[8][4];
        #pragma unroll
        for (int nt = 0; nt < 8; nt++)
            #pragma unroll
            for (int j = 0; j < 4; j++) sc[nt][j] = 0.f;
        #pragma unroll
        for (int ks2 = 0; ks2 < 4; ks2++) {
            uint32_t kfr[8][4];
            #pragma unroll
            for (int nt = 0; nt < 8; nt++) {
                int row = nt * 8 + (lane & 7);
                int chunk = ks2 * 4 + (lane >> 3);
                ldsm4(kfr[nt], sK + (uint32_t)(row * APAD + chunk * 4) * 4u);
            }
            #pragma unroll
            for (int kk = 0; kk < 2; kk++) {
                int ks = ks2 * 2 + kk;
                #pragma unroll
                for (int nt = 0; nt < 8; nt++)
                    mma_tf32(sc[nt], qa[ks], kfr[nt][kk*2], kfr[nt][kk*2+1]);
            }
        }

        #pragma unroll
        for (int nt = 0; nt < 8; nt++) {
            int c0 = nt * 8 + 2 * tg;
            bool ma = msk[c0] != 0, mb = msk[c0 + 1] != 0;
            sc[nt][0] = ma ? -1e30f : sc[nt][0] * 0.125f;
            sc[nt][1] = mb ? -1e30f : sc[nt][1] * 0.125f;
            sc[nt][2] = ma ? -1e30f : sc[nt][2] * 0.125f;
            sc[nt][3] = mb ? -1e30f : sc[nt][3] * 0.125f;
        }

        float rm0 = -INFINITY, rm1 = -INFINITY;
        #pragma unroll
        for (int nt = 0; nt < 8; nt++) {
            rm0 = fmaxf(rm0, fmaxf(sc[nt][0], sc[nt][1]));
            rm1 = fmaxf(rm1, fmaxf(sc[nt][2], sc[nt][3]));
        }
        rm0 = fmaxf(rm0, __shfl_xor_sync(0xffffffffu, rm0, 1));
        rm0 = fmaxf(rm0, __shfl_xor_sync(0xffffffffu, rm0, 2));
        rm1 = fmaxf(rm1, __shfl_xor_sync(0xffffffffu, rm1, 1));
        rm1 = fmaxf(rm1, __shfl_xor_sync(0xffffffffu, rm1, 2));
        float mn0 = fmaxf(m0, rm0), mn1 = fmaxf(m1, rm1);
        float cr0 = __expf(m0 - mn0), cr1 = __expf(m1 - mn1);
        m0 = mn0; m1 = mn1;
        float rs0 = 0.f, rs1 = 0.f;
        #pragma unroll
        for (int nt = 0; nt < 8; nt++) {
            sc[nt][0] = __expf(sc[nt][0] - mn0);
            sc[nt][1] = __expf(sc[nt][1] - mn0);
            sc[nt][2] = __expf(sc[nt][2] - mn1);
            sc[nt][3] = __expf(sc[nt][3] - mn1);
            rs0 += sc[nt][0] + sc[nt][1];
            rs1 += sc[nt][2] + sc[nt][3];
        }
        rs0 += __shfl_xor_sync(0xffffffffu, rs0, 1);
        rs0 += __shfl_xor_sync(0xffffffffu, rs0, 2);
        rs1 += __shfl_xor_sync(0xffffffffu, rs1, 1);
        rs1 += __shfl_xor_sync(0xffffffffu, rs1, 2);
        l0 = l0 * cr0 + rs0;
        l1 = l1 * cr1 + rs1;
        #pragma unroll
        for (int nt = 0; nt < 8; nt++) {
            oacc[nt][0] *= cr0; oacc[nt][1] *= cr0;
            oacc[nt][2] *= cr1; oacc[nt][3] *= cr1;
        }

        uint32_t pt[8][4];
        #pragma unroll
        for (int nt = 0; nt < 8; nt++)
            #pragma unroll
            for (int j = 0; j < 4; j++) pt[nt][j] = f2tf(sc[nt][j]);

        int sAl = qb + (tg >> 1), sBl = sAl + 2;
        bool odd = (tg & 1) != 0;
        #pragma unroll
        for (int ks2 = 0; ks2 < 4; ks2++) {
            uint32_t vfr[8][4];
            #pragma unroll
            for (int ntd = 0; ntd < 8; ntd++) {
                int row = ntd * 8 + (lane & 7);
                int chunk = ks2 * 4 + (lane >> 3);
                ldsm4(vfr[ntd], sV + (uint32_t)(row * APAD + chunk * 4) * 4u);
            }
            #pragma unroll
            for (int kk = 0; kk < 2; kk++) {
                int cnk = ks2 * 2 + kk;
                uint32_t x0 = __shfl_sync(0xffffffffu, pt[cnk][0], sAl);
                uint32_t x1 = __shfl_sync(0xffffffffu, pt[cnk][1], sAl);
                uint32_t x2 = __shfl_sync(0xffffffffu, pt[cnk][2], sAl);
                uint32_t x3 = __shfl_sync(0xffffffffu, pt[cnk][3], sAl);
                uint32_t y0 = __shfl_sync(0xffffffffu, pt[cnk][0], sBl);
                uint32_t y1 = __shfl_sync(0xffffffffu, pt[cnk][1], sBl);
                uint32_t y2 = __shfl_sync(0xffffffffu, pt[cnk][2], sBl);
                uint32_t y3 = __shfl_sync(0xffffffffu, pt[cnk][3], sBl);
                uint32_t af[4];
                af[0] = odd ? x1 : x0;
                af[1] = odd ? x3 : x2;
                af[2] = odd ? y1 : y0;
                af[3] = odd ? y3 : y2;
                #pragma unroll
                for (int ntd = 0; ntd < 8; ntd++)
                    mma_tf32(oacc[ntd], af, vfr[ntd][kk*2], vfr[ntd][kk*2+1]);
            }
        }
        __syncthreads();
    }

    float il0 = 1.f / l0, il1 = 1.f / l1;
    float* Ob = O + ((size_t)(b * SEQ + qw)) * DMODEL + h * DKH;
    #pragma unroll
    for (int ntd = 0; ntd < 8; ntd++) {
        int dc = ntd * 8 + 2 * tg;
        float2 o0 = {oacc[ntd][0] * il0, oacc[ntd][1] * il0};
        float2 o1 = {oacc[ntd][2] * il1, oacc[ntd][3] * il1};
        *(float2*)(Ob + (size_t)gr * DMODEL + dc) = o0;
        *(float2*)(Ob + (size_t)(gr + 8) * DMODEL + dc) = o1;
    }
}

// ---------------- driver -----------------------------------------------------
static float* sym_addr(const void* sym) {
    void* p = nullptr;
    cudaGetSymbolAddress(&p, sym);
    return (float*)p;
}

extern "C" void kernel_launch(void* const* d_in, const int* in_sizes, int n_in,
                              void* d_out, int out_size)
{
    const float*         x     = (const float*)d_in[0];
    const unsigned char* mask  = (const unsigned char*)d_in[1];
    const float*         W_Q   = (const float*)d_in[2];
    const float*         W_K   = (const float*)d_in[3];
    const float*         W_V   = (const float*)d_in[4];
    const float*         W_O   = (const float*)d_in[5];
    const float*         W1    = (const float*)d_in[6];
    const float*         b1    = (const float*)d_in[7];
    const float*         W2    = (const float*)d_in[8];
    const float*         b2    = (const float*)d_in[9];
    const float*         g1    = (const float*)d_in[10];
    const float*         beta1 = (const float*)d_in[11];
    const float*         g2    = (const float*)d_in[12];
    const float*         beta2 = (const float*)d_in[13];
    float* out = (float*)d_out;

    float* h  = sym_addr(g_h);
    float* q  = sym_addr(g_q);
    float* k  = sym_addr(g_k);
    float* v  = sym_addr(g_v);
    float* a  = sym_addr(g_a);
    float* x2 = sym_addr(g_x2);
    float* f1 = sym_addr(g_f1);

    const int M = MROWS;
    dim3 blk(256);
    dim3 gD (DMODEL/128, M/128);
    dim3 gF (DFF/128,    M/128);

    layernorm_k<<<M, blk>>>(x, g1, beta1, h);
    gemm_tc<false,false><<<gD, blk>>>(h, W_Q, nullptr, nullptr, q, M, DMODEL, DMODEL);
    gemm_tc<false,false><<<gD, blk>>>(h, W_K, nullptr, nullptr, k, M, DMODEL, DMODEL);
    gemm_tc<false,false><<<gD, blk>>>(h, W_V, nullptr, nullptr, v, M, DMODEL, DMODEL);
    attn_tc<<<dim3(SEQ/64, BATCH*NHEADS), 128>>>(q, k, v, mask, a);
    gemm_tc<false,true><<<gD, blk>>>(a, W_O, nullptr, x, x2, M, DMODEL, DMODEL);
    layernorm_k<<<M, blk>>>(x2, g2, beta2, h);
    gemm_tc<false,false><<<gF, blk>>>(h, W1, b1, nullptr, f1, M, DFF, DMODEL);
    gemm_tc<true,true><<<gD, blk>>>(f1, W2, b2, x2, out, M, DMODEL, DFF);
}